// round 2
// baseline (speedup 1.0000x reference)
#include <cuda_runtime.h>
#include <cuda_bf16.h>
#include <cstdint>

// Problem constants (from reference): B=4, NV=50000, NRINGS=3, NDIRS=16, NF=16
#define NV      50000
#define NRINGS  3
#define NDIRS   16
#define NF      16
#define VPB     16            // vertices per block
#define THREADS 256

// smem Y layout: per vertex stride 304 floats (== 16 mod 32 -> the two vertices
// in a warp use disjoint bank halves during phase 2). Within a vertex:
// [r][k][32] with entries d = 0..30 holding yrot[(d) % 16] (circular dup).
#define Y_VSTRIDE 304

// Packed fp32x2 FMA (Blackwell): acc += a * b, two fp32 lanes per instruction.
#define FMA_F32X2(acc, a, b) \
    asm("fma.rn.f32x2 %0, %1, %2, %0;" : "+l"(acc) : "l"(a), "l"(b))

#define PACK_F32X2(out, lo, hi) \
    asm("mov.b64 %0, {%1, %2};" : "=l"(out) : "r"(lo), "r"(hi))

#define UNPACK_F32X2(lo, hi, in) \
    asm("mov.b64 {%0, %1}, %2;" : "=r"(lo), "=r"(hi) : "l"(in))

__global__ void __launch_bounds__(THREADS)
geoconv_kernel(const float* __restrict__ basepoints,   // (B*NV, 3)
               const float* __restrict__ frames,       // (B*NV, 3, 3)
               const int*   __restrict__ expmap,       // (B*NV, 3, 16, 2)
               const float* __restrict__ kern,         // (3, 16, 3, 16)
               const float* __restrict__ bias,         // (16,)
               float* __restrict__ out)                // (B*NV, 16, 16)
{
    __shared__ float Ks[NRINGS * NDIRS * 3 * NF];      // 2304 floats, layout [r][w][c][f]
    __shared__ float Ys[VPB * Y_VSTRIDE];              // 4864 floats
    __shared__ float Bs[NF];

    const int tid = threadIdx.x;

    // --- stage conv weights (global layout already [r][w][c][f]) ---
    #pragma unroll
    for (int i = 0; i < 9; i++) Ks[tid + i * THREADS] = kern[tid + i * THREADS];
    if (tid < NF) Bs[tid] = bias[tid];

    const int vl = tid >> 4;          // local vertex 0..15
    const int d  = tid & 15;          // direction lane 0..15
    const int g  = blockIdx.x * VPB + vl;   // global flat vertex index (b*NV + v)

    // --- phase 1: gather neighbors, center, rotate into local frame ---
    const float bp0 = basepoints[g * 3 + 0];
    const float bp1 = basepoints[g * 3 + 1];
    const float bp2 = basepoints[g * 3 + 2];
    float F[9];
    #pragma unroll
    for (int i = 0; i < 9; i++) F[i] = frames[g * 9 + i];

    const int2* em = reinterpret_cast<const int2*>(expmap);
    #pragma unroll
    for (int r = 0; r < NRINGS; r++) {
        int2 e = em[(g * NRINGS + r) * NDIRS + d];       // {batch, vertex}
        const float* nb = basepoints + ((long long)e.x * NV + e.y) * 3;
        float y0 = nb[0] - bp0;
        float y1 = nb[1] - bp1;
        float y2 = nb[2] - bp2;
        #pragma unroll
        for (int k = 0; k < 3; k++) {
            float yr = F[k * 3 + 0] * y0 + F[k * 3 + 1] * y1 + F[k * 3 + 2] * y2;
            int base = vl * Y_VSTRIDE + (r * 3 + k) * 32;
            Ys[base + d] = yr;
            if (d < 15) Ys[base + d + 16] = yr;          // circular duplication
        }
    }
    __syncthreads();

    // --- phase 2: circular patch conv, thread = (vertex, out-dir j=d) ---
    // out[j][f] = sum_{r,w,c} Y[r][(j+w)][c] * K[r][w][c][f]  (Y duplicated => linear idx)
    unsigned long long acc[NF / 2];
    #pragma unroll
    for (int p = 0; p < NF / 2; p++) {
        PACK_F32X2(acc[p], __float_as_uint(Bs[2 * p]), __float_as_uint(Bs[2 * p + 1]));
    }

    const float* yrow = Ys + vl * Y_VSTRIDE + d;

    #pragma unroll
    for (int r = 0; r < NRINGS; r++) {
        #pragma unroll 8
        for (int w = 0; w < NDIRS; w++) {
            #pragma unroll
            for (int c = 0; c < 3; c++) {
                float yv = yrow[(r * 3 + c) * 32 + w];
                unsigned long long yy;
                PACK_F32X2(yy, __float_as_uint(yv), __float_as_uint(yv));
                const ulonglong2* kp = reinterpret_cast<const ulonglong2*>(
                    Ks + ((r * NDIRS + w) * 3 + c) * NF);
                ulonglong2 kA = kp[0];   // f 0..3   (broadcast across warp)
                ulonglong2 kB = kp[1];   // f 4..7
                ulonglong2 kC = kp[2];   // f 8..11
                ulonglong2 kD = kp[3];   // f 12..15
                FMA_F32X2(acc[0], yy, kA.x);
                FMA_F32X2(acc[1], yy, kA.y);
                FMA_F32X2(acc[2], yy, kB.x);
                FMA_F32X2(acc[3], yy, kB.y);
                FMA_F32X2(acc[4], yy, kC.x);
                FMA_F32X2(acc[5], yy, kC.y);
                FMA_F32X2(acc[6], yy, kD.x);
                FMA_F32X2(acc[7], yy, kD.y);
            }
        }
    }

    // --- bias already folded in; relu + vectorized store ---
    float res[NF];
    #pragma unroll
    for (int p = 0; p < NF / 2; p++) {
        unsigned int lo, hi;
        UNPACK_F32X2(lo, hi, acc[p]);
        res[2 * p]     = fmaxf(__uint_as_float(lo), 0.0f);
        res[2 * p + 1] = fmaxf(__uint_as_float(hi), 0.0f);
    }
    float4* op = reinterpret_cast<float4*>(out + ((long long)g * NDIRS + d) * NF);
    op[0] = make_float4(res[0],  res[1],  res[2],  res[3]);
    op[1] = make_float4(res[4],  res[5],  res[6],  res[7]);
    op[2] = make_float4(res[8],  res[9],  res[10], res[11]);
    op[3] = make_float4(res[12], res[13], res[14], res[15]);
}

extern "C" void kernel_launch(void* const* d_in, const int* in_sizes, int n_in,
                              void* d_out, int out_size)
{
    const float* basepoints = (const float*)d_in[0];   // (B, NV, 3)
    const float* frames     = (const float*)d_in[1];   // (B, NV, 3, 3)
    const int*   expmap     = (const int*)  d_in[2];   // (B, NV, 3, 16, 2)
    const float* kern       = (const float*)d_in[3];   // (3, 16, 3, 16)
    const float* bias       = (const float*)d_in[4];   // (16,)
    float*       out        = (float*)d_out;           // (B, NV, 16, 16)

    int total_verts = in_sizes[0] / 3;                 // B*NV = 200000
    int blocks = total_verts / VPB;                    // 12500

    geoconv_kernel<<<blocks, THREADS>>>(basepoints, frames, expmap, kern, bias, out);
}

// round 3
// speedup vs baseline: 1.9833x; 1.9833x over previous
#include <cuda_runtime.h>
#include <cuda_bf16.h>
#include <cstdint>

// Problem constants: B=4, NV=50000, NRINGS=3, NDIRS=16, NF=16
#define NV      50000
#define NRINGS  3
#define NDIRS   16
#define NF      16
#define VPB     16            // vertices per block
#define THREADS 256

// Packed fp32x2 FMA (Blackwell): acc += a * b, two fp32 lanes per instruction.
#define FMA_F32X2(acc, a, b) \
    asm("fma.rn.f32x2 %0, %1, %2, %0;" : "+l"(acc) : "l"(a), "l"(b))

#define PACK_F32X2(out, lo, hi) \
    asm("mov.b64 %0, {%1, %2};" : "=l"(out) : "r"(lo), "r"(hi))

#define UNPACK_F32X2(lo, hi, in) \
    asm("mov.b64 {%0, %1}, %2;" : "=r"(lo), "=r"(hi) : "l"(in))

__global__ void __launch_bounds__(THREADS)
geoconv_kernel(const float* __restrict__ basepoints,   // (B*NV, 3)
               const float* __restrict__ frames,       // (B*NV, 3, 3)
               const int*   __restrict__ expmap,       // (B*NV, 3, 16, 2)
               const float* __restrict__ kern,         // (3, 16, 3, 16)
               const float* __restrict__ bias,         // (16,)
               float* __restrict__ out)                // (B*NV, 16, 16)
{
    // Packed kernel pairs: Kp[rc][e][f] = { lo = K[r][e][c][f], hi = K[r][(e-1)&15][c][f] }
    __shared__ unsigned long long Kp[9 * 16 * NF];     // 2304 u64 = 18432 B
    // Rotated neighbor coords: Ys[vl][rc][p], vertex stride 144 (mod 32 = 16)
    __shared__ float Ys[VPB * 9 * 16];                 // 9216 B

    const int tid = threadIdx.x;
    const int vl  = tid >> 4;                 // local vertex 0..15
    const int lf  = tid & 15;                 // lane-in-vertex: f in phase2, d in phase1
    const int g   = blockIdx.x * VPB + vl;    // global flat vertex index

    // --- phase 0: build packed kernel pairs in smem ---
    #pragma unroll
    for (int it = 0; it < 9; it++) {
        int i  = tid + it * THREADS;          // 0..2303
        int f  = i & 15;
        int e  = (i >> 4) & 15;
        int rc = i >> 8;                      // 0..8
        int r  = rc / 3, c = rc % 3;
        float lo = kern[((r * 16 + e) * 3 + c) * NF + f];
        float hi = kern[((r * 16 + ((e + 15) & 15)) * 3 + c) * NF + f];
        unsigned long long pk;
        PACK_F32X2(pk, __float_as_uint(lo), __float_as_uint(hi));
        Kp[i] = pk;
    }

    // --- phase 1: gather neighbors, center, rotate into local frame ---
    {
        const int d = lf;
        const float bp0 = basepoints[g * 3 + 0];
        const float bp1 = basepoints[g * 3 + 1];
        const float bp2 = basepoints[g * 3 + 2];
        float F[9];
        #pragma unroll
        for (int i = 0; i < 9; i++) F[i] = frames[g * 9 + i];

        const int2* em = reinterpret_cast<const int2*>(expmap);
        #pragma unroll
        for (int r = 0; r < NRINGS; r++) {
            int2 e = em[(g * NRINGS + r) * NDIRS + d];     // {batch, vertex}
            const float* nb = basepoints + ((long long)e.x * NV + e.y) * 3;
            float y0 = nb[0] - bp0;
            float y1 = nb[1] - bp1;
            float y2 = nb[2] - bp2;
            #pragma unroll
            for (int k = 0; k < 3; k++) {
                float yr = F[k * 3 + 0] * y0 + F[k * 3 + 1] * y1 + F[k * 3 + 2] * y2;
                Ys[vl * 144 + (r * 3 + k) * 16 + d] = yr;
            }
        }
    }
    __syncthreads();

    // --- phase 2: circular conv; thread = (vertex, f), accumulators over j ---
    // acc[a] packs (out[j=2a][f], out[j=2a+1][f])
    const float bf = bias[lf];
    unsigned long long acc[8];
    #pragma unroll
    for (int a = 0; a < 8; a++) {
        PACK_F32X2(acc[a], __float_as_uint(bf), __float_as_uint(bf));
    }

    const float* yv = Ys + vl * 144;

    #pragma unroll 1
    for (int rc = 0; rc < 9; rc++) {
        // load 16 packed K pairs for this (r,c), held in registers for whole p-loop
        unsigned long long Kreg[16];
        const unsigned long long* kp = Kp + rc * 16 * NF + lf;
        #pragma unroll
        for (int e = 0; e < 16; e++) Kreg[e] = kp[e * NF];

        const float* yrow = yv + rc * 16;
        #pragma unroll
        for (int p = 0; p < 16; p++) {
            float y = yrow[p];                          // warp-broadcast LDS
            unsigned long long yy;
            PACK_F32X2(yy, __float_as_uint(y), __float_as_uint(y));
            #pragma unroll
            for (int a = 0; a < 8; a++) {
                const int e = (p - 2 * a) & 15;         // compile-time
                FMA_F32X2(acc[a], yy, Kreg[e]);
            }
        }
    }

    // --- relu + store: out[g][j][f], j from acc pairs ---
    float* ob = out + ((long long)g * NDIRS) * NF + lf;
    #pragma unroll
    for (int a = 0; a < 8; a++) {
        unsigned int lo, hi;
        UNPACK_F32X2(lo, hi, acc[a]);
        ob[(2 * a) * NF]     = fmaxf(__uint_as_float(lo), 0.0f);
        ob[(2 * a + 1) * NF] = fmaxf(__uint_as_float(hi), 0.0f);
    }
}

extern "C" void kernel_launch(void* const* d_in, const int* in_sizes, int n_in,
                              void* d_out, int out_size)
{
    const float* basepoints = (const float*)d_in[0];   // (B, NV, 3)
    const float* frames     = (const float*)d_in[1];   // (B, NV, 3, 3)
    const int*   expmap     = (const int*)  d_in[2];   // (B, NV, 3, 16, 2)
    const float* kern       = (const float*)d_in[3];   // (3, 16, 3, 16)
    const float* bias       = (const float*)d_in[4];   // (16,)
    float*       out        = (float*)d_out;           // (B, NV, 16, 16)

    int total_verts = in_sizes[0] / 3;                 // B*NV = 200000
    int blocks = total_verts / VPB;                    // 12500

    geoconv_kernel<<<blocks, THREADS>>>(basepoints, frames, expmap, kern, bias, out);
}